// round 16
// baseline (speedup 1.0000x reference)
#include <cuda_runtime.h>
#include <math.h>

#define Bb 4
#define Ss 1024
#define Dd 512
#define Hh 8
#define DHd 64
#define SST 1034   // sbuf row stride (floats): conflict-free for 2/4-row strides

typedef unsigned long long ull;

__device__ __constant__ float kScale = 0.044194173824159216f; // 1/sqrt(512)

// ---- packed f32x2 helpers (sm_103a) ----
__device__ __forceinline__ ull pk2(float x, float y) {
    ull r; asm("mov.b64 %0, {%1, %2};" : "=l"(r) : "f"(x), "f"(y)); return r;
}
__device__ __forceinline__ ull splat2(float x) {
    ull r; asm("mov.b64 %0, {%1, %1};" : "=l"(r) : "f"(x)); return r;
}
__device__ __forceinline__ float lo2(ull v) { return __uint_as_float((unsigned)v); }
__device__ __forceinline__ float hi2(ull v) { return __uint_as_float((unsigned)(v >> 32)); }
__device__ __forceinline__ void fma2(ull& d, ull a, ull b) {
    asm("fma.rn.f32x2 %0, %1, %2, %0;" : "+l"(d) : "l"(a), "l"(b));
}
__device__ __forceinline__ float red2(ull v) { return lo2(v) + hi2(v); }

__device__ __forceinline__ unsigned smem_u32(const void* p) {
    return (unsigned)__cvta_generic_to_shared(p);
}
// volatile: real memory reads — must not be hoisted across C++ smem stores /
// __syncthreads() (R8 failure root cause).
__device__ __forceinline__ void lds2x64(ull& a, ull& b, unsigned addr) {
    asm volatile("ld.shared.v2.b64 {%0,%1}, [%2];" : "=l"(a), "=l"(b) : "r"(addr));
}
__device__ __forceinline__ float lds32(unsigned addr) {
    float v; asm volatile("ld.shared.f32 %0, [%1];" : "=f"(v) : "r"(addr)); return v;
}

// ---- tf32 mma helpers ----
__device__ __forceinline__ unsigned cvt_tf32(float x) {
    unsigned r; asm("cvt.rna.tf32.f32 %0, %1;" : "=r"(r) : "f"(x)); return r;
}
__device__ __forceinline__ void mma_tf32(
    float& d0, float& d1, float& d2, float& d3,
    unsigned a0, unsigned a1, unsigned a2, unsigned a3,
    unsigned b0, unsigned b1)
{
    asm volatile(
        "mma.sync.aligned.m16n8k8.row.col.f32.tf32.tf32.f32 "
        "{%0,%1,%2,%3}, {%4,%5,%6,%7}, {%8,%9}, {%0,%1,%2,%3};"
        : "+f"(d0), "+f"(d1), "+f"(d2), "+f"(d3)
        : "r"(a0), "r"(a1), "r"(a2), "r"(a3), "r"(b0), "r"(b1));
}

// scratch: 11 chunks of B*S*D floats
#define CHUNK ((size_t)Bb * Ss * Dd)  // 2097152
__device__ float g_scratch[CHUNK * 11];

#define OFF_QU1 (0 * CHUNK)
#define OFF_QV1 (1 * CHUNK)
#define OFF_K1  (2 * CHUNK)
#define OFF_V1  (3 * CHUNK)
#define OFF_QU2 (4 * CHUNK)
#define OFF_QV2 (5 * CHUNK)
#define OFF_K2  (6 * CHUNK)
#define OFF_V2  (7 * CHUNK)
#define OFF_POS (8 * CHUNK)
#define OFF_CTX1 (9 * CHUNK)
#define OFF_CTX2 (10 * CHUNK)

// d_out offsets (floats)
#define OFF_CTX1OUT ((size_t)0)
#define OFF_ATTN1   ((size_t)2097152)
#define OFF_CTX2OUT ((size_t)35651584)
#define OFF_ATTN2   ((size_t)37748736)

// ---------------------------------------------------------------------------
// Batched tf32 SGEMM: C[4096,512] = A[4096,512] @ W[512,512] (+bias)
// 128x128 block tile, 8 warps x (32x64), k16 slabs double-buffered, m16n8k8.
// k-rows stored physically permuted by pi(k)=(k&3)*4+(k>>2) on BOTH A and W
// (sum over k is permutation-invariant) -> conflict-free stores AND reads.
// ---------------------------------------------------------------------------
struct GDesc {
    const float* A; const float* W; const float* bias;
    float* d0; float* d1;
    const float* e0; const float* e1;
    long long mode;
};
struct GDescArr { GDesc g[8]; };

__global__ __launch_bounds__(256, 2)
void sgemm_tf32(GDescArr P)
{
    GDesc gd = P.g[blockIdx.z];
    __shared__ unsigned As[2][16][136];
    __shared__ unsigned Ws[2][16][136];
    int tid = threadIdx.x;
    int w = tid >> 5, lane = tid & 31;
    int g = lane >> 2, tg = lane & 3;
    int bx = blockIdx.x, by = blockIdx.y;
    int rwarp = (w >> 1) * 32;
    int cwarp = (w & 1) * 64;

    float acc[2][8][4];
#pragma unroll
    for (int m = 0; m < 2; m++)
#pragma unroll
        for (int nt = 0; nt < 8; nt++)
#pragma unroll
            for (int e = 0; e < 4; e++) acc[m][nt][e] = 0.f;

    int arow = tid >> 2, ajj = tid & 3;     // A f4: rows 0..63 (+64 second)
    int wkr = tid >> 5, wnn = tid & 31;     // W f4: k-rows 0..7 (+8 second)
    int wpr0 = (wkr & 3) * 4 + (wkr >> 2);          // pi(wkr)
    int wpr1 = ((wkr + 8) & 3) * 4 + ((wkr + 8) >> 2);

    const float* Ab = gd.A + (size_t)(by * 128) * 512;
    const float* Wb = gd.W + bx * 128;

    float4 a0v, a1v, w0v, w1v;
    a0v = *(const float4*)(Ab + (size_t)arow * 512 + ajj * 4);
    a1v = *(const float4*)(Ab + (size_t)(arow + 64) * 512 + ajj * 4);
    w0v = *(const float4*)(Wb + (size_t)wkr * 512 + wnn * 4);
    w1v = *(const float4*)(Wb + (size_t)(wkr + 8) * 512 + wnn * 4);
    {
        // A element logical k = ajj*4+c stored at physical row c*4+ajj
        As[0][0 * 4 + ajj][arow] = cvt_tf32(a0v.x);
        As[0][1 * 4 + ajj][arow] = cvt_tf32(a0v.y);
        As[0][2 * 4 + ajj][arow] = cvt_tf32(a0v.z);
        As[0][3 * 4 + ajj][arow] = cvt_tf32(a0v.w);
        As[0][0 * 4 + ajj][arow + 64] = cvt_tf32(a1v.x);
        As[0][1 * 4 + ajj][arow + 64] = cvt_tf32(a1v.y);
        As[0][2 * 4 + ajj][arow + 64] = cvt_tf32(a1v.z);
        As[0][3 * 4 + ajj][arow + 64] = cvt_tf32(a1v.w);
        *(uint4*)&Ws[0][wpr0][wnn * 4] = make_uint4(
            cvt_tf32(w0v.x), cvt_tf32(w0v.y), cvt_tf32(w0v.z), cvt_tf32(w0v.w));
        *(uint4*)&Ws[0][wpr1][wnn * 4] = make_uint4(
            cvt_tf32(w1v.x), cvt_tf32(w1v.y), cvt_tf32(w1v.z), cvt_tf32(w1v.w));
    }
    __syncthreads();

#pragma unroll 1
    for (int kk = 0; kk < 32; kk++) {
        int buf = kk & 1;
        if (kk < 31) {
            int kb16 = (kk + 1) * 16;
            a0v = *(const float4*)(Ab + (size_t)arow * 512 + kb16 + ajj * 4);
            a1v = *(const float4*)(Ab + (size_t)(arow + 64) * 512 + kb16 + ajj * 4);
            w0v = *(const float4*)(Wb + (size_t)(kb16 + wkr) * 512 + wnn * 4);
            w1v = *(const float4*)(Wb + (size_t)(kb16 + wkr + 8) * 512 + wnn * 4);
        }
#pragma unroll
        for (int ks = 0; ks < 16; ks += 8) {
            unsigned a[2][4];
#pragma unroll
            for (int m = 0; m < 2; m++) {
                int rb = rwarp + m * 16;
                a[m][0] = As[buf][ks + tg][rb + g];
                a[m][1] = As[buf][ks + tg][rb + g + 8];
                a[m][2] = As[buf][ks + tg + 4][rb + g];
                a[m][3] = As[buf][ks + tg + 4][rb + g + 8];
            }
#pragma unroll
            for (int nt = 0; nt < 8; nt++) {
                unsigned b0 = Ws[buf][ks + tg][cwarp + nt * 8 + g];
                unsigned b1 = Ws[buf][ks + tg + 4][cwarp + nt * 8 + g];
                mma_tf32(acc[0][nt][0], acc[0][nt][1], acc[0][nt][2], acc[0][nt][3],
                         a[0][0], a[0][1], a[0][2], a[0][3], b0, b1);
                mma_tf32(acc[1][nt][0], acc[1][nt][1], acc[1][nt][2], acc[1][nt][3],
                         a[1][0], a[1][1], a[1][2], a[1][3], b0, b1);
            }
        }
        if (kk < 31) {
            int nb = buf ^ 1;
            As[nb][0 * 4 + ajj][arow] = cvt_tf32(a0v.x);
            As[nb][1 * 4 + ajj][arow] = cvt_tf32(a0v.y);
            As[nb][2 * 4 + ajj][arow] = cvt_tf32(a0v.z);
            As[nb][3 * 4 + ajj][arow] = cvt_tf32(a0v.w);
            As[nb][0 * 4 + ajj][arow + 64] = cvt_tf32(a1v.x);
            As[nb][1 * 4 + ajj][arow + 64] = cvt_tf32(a1v.y);
            As[nb][2 * 4 + ajj][arow + 64] = cvt_tf32(a1v.z);
            As[nb][3 * 4 + ajj][arow + 64] = cvt_tf32(a1v.w);
            *(uint4*)&Ws[nb][wpr0][wnn * 4] = make_uint4(
                cvt_tf32(w0v.x), cvt_tf32(w0v.y), cvt_tf32(w0v.z), cvt_tf32(w0v.w));
            *(uint4*)&Ws[nb][wpr1][wnn * 4] = make_uint4(
                cvt_tf32(w1v.x), cvt_tf32(w1v.y), cvt_tf32(w1v.z), cvt_tf32(w1v.w));
            __syncthreads();
        }
    }

    int mode = (int)gd.mode;
#pragma unroll
    for (int m = 0; m < 2; m++) {
        int r0 = by * 128 + rwarp + m * 16 + g;
#pragma unroll
        for (int nt = 0; nt < 8; nt++) {
            int c0 = bx * 128 + cwarp + nt * 8 + 2 * tg;
#pragma unroll
            for (int e = 0; e < 4; e++) {
                int gr = r0 + (e >> 1) * 8;
                int gc = c0 + (e & 1);
                float v = acc[m][nt][e] + (gd.bias ? gd.bias[gc] : 0.f);
                if (mode == 0) {
                    gd.d0[(size_t)gr * 512 + gc] = v;
                } else {
                    int h = gc >> 6, d = gc & 63;
                    int bI = gr >> 10, sI = gr & 1023;
                    size_t off = (((size_t)(bI * Hh + h) * Ss + sI) * DHd + d);
                    if (mode == 1) {
                        gd.d0[off] = v;
                    } else {
                        gd.d0[off] = v + gd.e0[gc];
                        gd.d1[off] = v + gd.e1[gc];
                    }
                }
            }
        }
    }
}

// ---------------------------------------------------------------------------
// Fused attention kernel (unchanged from R15 — validated at 1219us/3.05e-4)
// ---------------------------------------------------------------------------
__global__ __launch_bounds__(512, 2)
void attn_kernel(float* __restrict__ scratch,
                 const unsigned char* __restrict__ maskg,
                 float* __restrict__ out)
{
    extern __shared__ float sm[];
    float* qu   = sm;                 // [16][68] tf32-bit u32 (as float storage)
    float* qv   = sm + 1088;          // [17][68] tf32-bit u32
    float* kb   = sm + 2244;          // [128][68] = 8704 (tile / reduce buffer)
    float* sbuf = sm + 10948;         // [16][SST] = 16544 (scores -> prob bits)
    unsigned char* msk = (unsigned char*)(sm + 27492); // 1024 B

    int tid = threadIdx.x;
    int lane = tid & 31, w = tid >> 5;   // w 0..15
    int tile = blockIdx.x;   // 0..63
    int h = blockIdx.y;      // 0..7
    int bz = blockIdx.z;     // 0..7
    int bI = bz >> 1, st = bz & 1;

    const float* QUg = scratch + (st ? OFF_QU2 : OFF_QU1);
    const float* QVg = scratch + (st ? OFF_QV2 : OFF_QV1);
    const float* Kg  = scratch + (st ? OFF_K2  : OFF_K1);
    const float* Vg  = scratch + (st ? OFF_V2  : OFF_V1);
    const float* Pg  = scratch + OFF_POS;
    float* CTXg = scratch + (st ? OFF_CTX2 : OFF_CTX1);

    size_t bh = (size_t)(bI * Hh + h) * Ss * DHd;

    unsigned* quw = (unsigned*)qu;
    unsigned* qvw = (unsigned*)qv;

    // ---- phase 0: q loads pre-converted to tf32 bits, mask ----
#pragma unroll
    for (int it = 0; it < 2; it++) {
        int idx = it * 512 + tid;                // 0..1023
        int r = idx >> 6, d = idx & 63;
        quw[r * 68 + d] = cvt_tf32(QUg[bh + (size_t)(tile * 16 + r) * 64 + d]);
    }
#pragma unroll
    for (int it = 0; it < 3; it++) {
        int idx = it * 512 + tid;
        if (idx < 1088) {
            int r = idx >> 6, d = idx & 63;
            int gi = tile * 16 + r;
            if (gi > Ss - 1) gi = Ss - 1;        // row16 of last tile: blocked below
            qvw[r * 68 + d] = cvt_tf32(QVg[bh + (size_t)gi * 64 + d]);
        }
    }
    {
        const unsigned char* mrow = maskg + (size_t)bI * Ss;
#pragma unroll
        for (int it = 0; it < 2; it++) {
            int idx = it * 512 + tid;
            msk[idx] = mrow[idx];
        }
    }
    __syncthreads();

    unsigned qv_u = smem_u32(qv);
    unsigned kb_u = smem_u32(kb);

    int g  = lane >> 2;   // mma group 0..7
    int tg = lane & 3;    // thread-in-group 0..3

    // ================= pass 1: content -> sbuf (tf32 mma) =================
    {
        float4 fl[4];
#pragma unroll
        for (int it = 0; it < 4; it++) {
            int idx = it * 512 + tid; int s_ = idx >> 4, ds = idx & 15;
            fl[it] = *(const float4*)(Kg + bh + (size_t)s_ * 64 + ds * 4);
        }
#pragma unroll 1
        for (int c = 0; c < 8; c++) {
#pragma unroll
            for (int it = 0; it < 4; it++) {
                int idx = it * 512 + tid; int s_ = idx >> 4, ds = idx & 15;
                *(float4*)(kb + s_ * 68 + ds * 4) = fl[it];
            }
            __syncthreads();
            if (c < 7) {
#pragma unroll
                for (int it = 0; it < 4; it++) {
                    int idx = it * 512 + tid; int s_ = idx >> 4, ds = idx & 15;
                    fl[it] = *(const float4*)(Kg + bh
                                  + (size_t)((c + 1) * 128 + s_) * 64 + ds * 4);
                }
            }
            float d0 = 0.f, d1 = 0.f, d2 = 0.f, d3 = 0.f;
            const float* kcol = kb + (w * 8 + g) * 68;
#pragma unroll
            for (int ks = 0; ks < 8; ks++) {
                unsigned a0 = quw[g * 68 + ks * 8 + tg];
                unsigned a1 = quw[(g + 8) * 68 + ks * 8 + tg];
                unsigned a2 = quw[g * 68 + ks * 8 + tg + 4];
                unsigned a3 = quw[(g + 8) * 68 + ks * 8 + tg + 4];
                unsigned b0 = cvt_tf32(kcol[ks * 8 + tg]);
                unsigned b1 = cvt_tf32(kcol[ks * 8 + tg + 4]);
                mma_tf32(d0, d1, d2, d3, a0, a1, a2, a3, b0, b1);
            }
            int col = c * 128 + w * 8 + 2 * tg;
            *(float2*)&sbuf[g * SST + col] = make_float2(d0, d1);
            *(float2*)&sbuf[(g + 8) * SST + col] = make_float2(d2, d3);
            __syncthreads();
        }
    }

    // ================= pass 2: pos scatter-add into sbuf (tf32 mma) ========
    {
        float4 fl[4];
#pragma unroll
        for (int it = 0; it < 4; it++) {
            int idx = it * 512 + tid; int s_ = idx >> 4, ds = idx & 15;
            fl[it] = *(const float4*)(Pg + bh + (size_t)s_ * 64 + ds * 4);
        }
#pragma unroll 1
        for (int c = 0; c < 8; c++) {
#pragma unroll
            for (int it = 0; it < 4; it++) {
                int idx = it * 512 + tid; int s_ = idx >> 4, ds = idx & 15;
                *(float4*)(kb + s_ * 68 + ds * 4) = fl[it];
            }
            __syncthreads();
            if (c < 7) {
#pragma unroll
                for (int it = 0; it < 4; it++) {
                    int idx = it * 512 + tid; int s_ = idx >> 4, ds = idx & 15;
                    fl[it] = *(const float4*)(Pg + bh
                                  + (size_t)((c + 1) * 128 + s_) * 64 + ds * 4);
                }
            }
            float d0 = 0.f, d1 = 0.f, d2 = 0.f, d3 = 0.f;
            const float* pcol = kb + (w * 8 + g) * 68;
#pragma unroll
            for (int ks = 0; ks < 8; ks++) {
                unsigned a0 = qvw[g * 68 + ks * 8 + tg];
                unsigned a1 = qvw[(g + 8) * 68 + ks * 8 + tg];
                unsigned a2 = qvw[g * 68 + ks * 8 + tg + 4];
                unsigned a3 = qvw[(g + 8) * 68 + ks * 8 + tg + 4];
                unsigned b0 = cvt_tf32(pcol[ks * 8 + tg]);
                unsigned b1 = cvt_tf32(pcol[ks * 8 + tg + 4]);
                mma_tf32(d0, d1, d2, d3, a0, a1, a2, a3, b0, b1);
            }
            int cg0 = c * 128 + w * 8 + 2 * tg;
            float vv[4] = { d0, d1, d2, d3 };
            int rr[4]   = { g, g, g + 8, g + 8 };
            int cc[4]   = { cg0, cg0 + 1, cg0, cg0 + 1 };
#pragma unroll
            for (int j = 0; j < 4; j++) {
                int row = rr[j], cg = cc[j];
                int gg = tile * 16 + row;
                bool condA = (cg >= Ss - 1 - gg);
                int addr = condA ? (row * SST + (cg + gg + 1 - Ss))
                                 : ((row - 1) * SST + (cg + gg + 1));
                if (condA || row > 0) sbuf[addr] += vv[j];
            }
            if (w < 4) {   // extra pos row 16 -> contributes only to row 15 (fp32)
                int col16 = w * 32 + lane;
                unsigned q16_u = qv_u + 16u * 272;
                unsigned pc_u = kb_u + (unsigned)col16 * 272;
                ull a = 0;
#pragma unroll
                for (int dq = 0; dq < 16; dq++) {
                    ull q01, q23; lds2x64(q01, q23, q16_u + dq * 16);
                    ull p01, p23; lds2x64(p01, p23, pc_u + dq * 16);
                    fma2(a, q01, p01); fma2(a, q23, p23);
                }
                int g16 = tile * 16 + 16;
                int cg16 = c * 128 + col16;
                if (g16 <= Ss - 1 && cg16 <= Ss - 2 - g16)
                    sbuf[15 * SST + (cg16 + g16 + 1)] += red2(a);
            }
            __syncthreads();
        }
    }

    // ---- softmax (warp = 1 row), register array ----
    int r = w;
    int ig = tile * 16 + r;
    float s[32];

    float mx = -1e30f;
#pragma unroll
    for (int jp = 0; jp < 32; jp++) {
        int t = jp * 32 + lane;
        float sc = sbuf[r * SST + t] * kScale;
        if (msk[t]) sc = -1e9f;
        s[jp] = sc;
        mx = fmaxf(mx, sc);
    }
#pragma unroll
    for (int o = 16; o > 0; o >>= 1)
        mx = fmaxf(mx, __shfl_xor_sync(0xffffffffu, mx, o));
    float sum = 0.f;
#pragma unroll
    for (int jp = 0; jp < 32; jp++) {
        float e = __expf(s[jp] - mx); s[jp] = e; sum += e;
    }
#pragma unroll
    for (int o = 16; o > 0; o >>= 1)
        sum += __shfl_xor_sync(0xffffffffu, sum, o);
    float inv = 1.f / sum;

    __syncthreads();

    // ---- phase D: fp32 probs to gmem; tf32-bit probs into sbuf ----
    size_t aout = (st ? OFF_ATTN2 : OFF_ATTN1) + ((size_t)(bI * Hh + h) * Ss) * Ss;
    unsigned* sbw = (unsigned*)sbuf;
#pragma unroll
    for (int jp = 0; jp < 32; jp++) {
        int t = jp * 32 + lane;
        float p = s[jp] * inv;
        out[aout + (size_t)ig * Ss + t] = p;
        sbw[r * SST + t] = cvt_tf32(p);
    }
    __syncthreads();

    // ---- phase E: ctx = probs @ V via tf32 mma ----
    {
        int nbase = (w & 7) * 8;
        int kh = w >> 3;

        float d0 = 0.f, d1 = 0.f, d2 = 0.f, d3 = 0.f;

        float4 fl[4];
#pragma unroll
        for (int it = 0; it < 4; it++) {
            int idx = it * 512 + tid; int s_ = idx >> 4, ds = idx & 15;
            fl[it] = *(const float4*)(Vg + bh + (size_t)s_ * 64 + ds * 4);
        }
#pragma unroll 1
        for (int c = 0; c < 8; c++) {
#pragma unroll
            for (int it = 0; it < 4; it++) {
                int idx = it * 512 + tid; int s_ = idx >> 4, ds = idx & 15;
                *(float4*)(kb + s_ * 68 + ds * 4) = fl[it];
            }
            __syncthreads();
            if (c < 7) {
#pragma unroll
                for (int it = 0; it < 4; it++) {
                    int idx = it * 512 + tid; int s_ = idx >> 4, ds = idx & 15;
                    fl[it] = *(const float4*)(Vg + bh
                                  + (size_t)((c + 1) * 128 + s_) * 64 + ds * 4);
                }
            }
            int cbase = c * 128 + kh * 64;
            const float* vb2 = kb + (kh * 64) * 68 + nbase + g;
#pragma unroll
            for (int ks = 0; ks < 8; ks++) {
                int t0 = ks * 8;
                unsigned a0 = sbw[g * SST + cbase + t0 + tg];
                unsigned a1 = sbw[(g + 8) * SST + cbase + t0 + tg];
                unsigned a2 = sbw[g * SST + cbase + t0 + tg + 4];
                unsigned a3 = sbw[(g + 8) * SST + cbase + t0 + tg + 4];
                unsigned b0 = cvt_tf32(vb2[(t0 + tg) * 68]);
                unsigned b1 = cvt_tf32(vb2[(t0 + tg + 4) * 68]);
                mma_tf32(d0, d1, d2, d3, a0, a1, a2, a3, b0, b1);
            }
            __syncthreads();
        }

        // partials -> kb[kh][row][col] (stride 68), then 2-way reduce
        {
            float* red = kb + kh * 1100;
            *(float2*)&red[g * 68 + nbase + 2 * tg] = make_float2(d0, d1);
            *(float2*)&red[(g + 8) * 68 + nbase + 2 * tg] = make_float2(d2, d3);
        }
        __syncthreads();
        {
            int o = tid * 2;                  // 0..1022, 2 outputs per thread
            int row = o >> 6, dd = o & 63;
            float2 p0 = *(const float2*)&kb[row * 68 + dd];
            float2 p1 = *(const float2*)&kb[1100 + row * 68 + dd];
            float2 rr2 = make_float2(p0.x + p1.x, p0.y + p1.y);
            int gi = tile * 16 + row;
            *(float2*)(CTXg + ((size_t)(bI * Ss + gi)) * Dd + h * DHd + dd) = rr2;
        }
    }
}

// ---------------------------------------------------------------------------
extern "C" void kernel_launch(void* const* d_in, const int* in_sizes, int n_in,
                              void* d_out, int out_size)
{
    const float* x1  = (const float*)d_in[0];
    const float* x2  = (const float*)d_in[1];
    const float* pe  = (const float*)d_in[2];
    const unsigned char* mask = (const unsigned char*)d_in[3];
    const float* Wq  = (const float*)d_in[4];
    const float* bq  = (const float*)d_in[5];
    const float* Wk  = (const float*)d_in[6];
    const float* bk  = (const float*)d_in[7];
    const float* Wv  = (const float*)d_in[8];
    const float* bv  = (const float*)d_in[9];
    const float* Wp  = (const float*)d_in[10];
    const float* ub  = (const float*)d_in[11];
    const float* vb  = (const float*)d_in[12];
    const float* Wo1 = (const float*)d_in[13];
    const float* bo1 = (const float*)d_in[14];
    const float* Wo2 = (const float*)d_in[15];
    const float* bo2 = (const float*)d_in[16];
    float* out = (float*)d_out;

    float* scratch = nullptr;
    cudaGetSymbolAddress((void**)&scratch, g_scratch);

    const int attn_smem = 27492 * 4 + 1024;  // 110,992 B -> 2 blocks/SM
    cudaFuncSetAttribute(attn_kernel, cudaFuncAttributeMaxDynamicSharedMemorySize,
                         attn_smem);

    // batched projections (7 GEMMs in one launch, tf32)
    GDescArr pj{};
    pj.g[0] = { x1, Wq, bq, scratch + OFF_QU1, scratch + OFF_QV1, ub, vb, 2 };
    pj.g[1] = { x1, Wk, bk, scratch + OFF_K1,  nullptr, nullptr, nullptr, 1 };
    pj.g[2] = { x1, Wv, bv, scratch + OFF_V1,  nullptr, nullptr, nullptr, 1 };
    pj.g[3] = { x2, Wq, bq, scratch + OFF_QU2, scratch + OFF_QV2, ub, vb, 2 };
    pj.g[4] = { x2, Wk, bk, scratch + OFF_K2,  nullptr, nullptr, nullptr, 1 };
    pj.g[5] = { x2, Wv, bv, scratch + OFF_V2,  nullptr, nullptr, nullptr, 1 };
    pj.g[6] = { pe, Wp, nullptr, scratch + OFF_POS, nullptr, nullptr, nullptr, 1 };
    sgemm_tf32<<<dim3(4, 32, 7), 256>>>(pj);

    // fused attention: tf32 scores + rel-shift(scatter) + softmax + tf32 ctx
    attn_kernel<<<dim3(64, 8, 8), 512, attn_smem>>>(scratch, mask, out);

    // batched output projections (2 GEMMs in one launch, tf32)
    GDescArr po{};
    po.g[0] = { scratch + OFF_CTX1, Wo1, bo1, out + OFF_CTX1OUT, nullptr, nullptr, nullptr, 0 };
    po.g[1] = { scratch + OFF_CTX2, Wo2, bo2, out + OFF_CTX2OUT, nullptr, nullptr, nullptr, 0 };
    sgemm_tf32<<<dim3(4, 32, 2), 256>>>(po);
}

// round 17
// speedup vs baseline: 1.0038x; 1.0038x over previous
#include <cuda_runtime.h>
#include <math.h>

#define Bb 4
#define Ss 1024
#define Dd 512
#define Hh 8
#define DHd 64
#define SST 1034   // sbuf row stride (floats): conflict-free for 2/4-row strides

typedef unsigned long long ull;

__device__ __constant__ float kScale = 0.044194173824159216f; // 1/sqrt(512)

// ---- packed f32x2 helpers (sm_103a) ----
__device__ __forceinline__ ull pk2(float x, float y) {
    ull r; asm("mov.b64 %0, {%1, %2};" : "=l"(r) : "f"(x), "f"(y)); return r;
}
__device__ __forceinline__ ull splat2(float x) {
    ull r; asm("mov.b64 %0, {%1, %1};" : "=l"(r) : "f"(x)); return r;
}
__device__ __forceinline__ float lo2(ull v) { return __uint_as_float((unsigned)v); }
__device__ __forceinline__ float hi2(ull v) { return __uint_as_float((unsigned)(v >> 32)); }
__device__ __forceinline__ void fma2(ull& d, ull a, ull b) {
    asm("fma.rn.f32x2 %0, %1, %2, %0;" : "+l"(d) : "l"(a), "l"(b));
}
__device__ __forceinline__ float red2(ull v) { return lo2(v) + hi2(v); }

__device__ __forceinline__ unsigned smem_u32(const void* p) {
    return (unsigned)__cvta_generic_to_shared(p);
}
// volatile: real memory reads — must not be hoisted across C++ smem stores /
// __syncthreads() (R8 failure root cause).
__device__ __forceinline__ void lds2x64(ull& a, ull& b, unsigned addr) {
    asm volatile("ld.shared.v2.b64 {%0,%1}, [%2];" : "=l"(a), "=l"(b) : "r"(addr));
}
__device__ __forceinline__ float lds32(unsigned addr) {
    float v; asm volatile("ld.shared.f32 %0, [%1];" : "=f"(v) : "r"(addr)); return v;
}

// ---- tf32 mma helpers ----
__device__ __forceinline__ unsigned cvt_tf32(float x) {
    unsigned r; asm("cvt.rna.tf32.f32 %0, %1;" : "=r"(r) : "f"(x)); return r;
}
__device__ __forceinline__ void mma_tf32(
    float& d0, float& d1, float& d2, float& d3,
    unsigned a0, unsigned a1, unsigned a2, unsigned a3,
    unsigned b0, unsigned b1)
{
    asm volatile(
        "mma.sync.aligned.m16n8k8.row.col.f32.tf32.tf32.f32 "
        "{%0,%1,%2,%3}, {%4,%5,%6,%7}, {%8,%9}, {%0,%1,%2,%3};"
        : "+f"(d0), "+f"(d1), "+f"(d2), "+f"(d3)
        : "r"(a0), "r"(a1), "r"(a2), "r"(a3), "r"(b0), "r"(b1));
}

// scratch: 11 chunks of B*S*D floats
#define CHUNK ((size_t)Bb * Ss * Dd)  // 2097152
__device__ float g_scratch[CHUNK * 11];

#define OFF_QU1 (0 * CHUNK)
#define OFF_QV1 (1 * CHUNK)
#define OFF_K1  (2 * CHUNK)
#define OFF_V1  (3 * CHUNK)
#define OFF_QU2 (4 * CHUNK)
#define OFF_QV2 (5 * CHUNK)
#define OFF_K2  (6 * CHUNK)
#define OFF_V2  (7 * CHUNK)
#define OFF_POS (8 * CHUNK)
#define OFF_CTX1 (9 * CHUNK)
#define OFF_CTX2 (10 * CHUNK)

// d_out offsets (floats)
#define OFF_CTX1OUT ((size_t)0)
#define OFF_ATTN1   ((size_t)2097152)
#define OFF_CTX2OUT ((size_t)35651584)
#define OFF_ATTN2   ((size_t)37748736)

// ---------------------------------------------------------------------------
// Batched tf32 SGEMM: C[4096,512] = A[4096,512] @ W[512,512] (+bias)
// 128x128 block tile, 8 warps x (32x64), k16 slabs double-buffered, m16n8k8.
// k-rows stored physically permuted by pi(k)=(k&3)*4+(k>>2) on BOTH A and W
// (sum over k is permutation-invariant) -> conflict-free stores AND reads.
// ---------------------------------------------------------------------------
struct GDesc {
    const float* A; const float* W; const float* bias;
    float* d0; float* d1;
    const float* e0; const float* e1;
    long long mode;
};
struct GDescArr { GDesc g[8]; };

__global__ __launch_bounds__(256, 2)
void sgemm_tf32(GDescArr P)
{
    GDesc gd = P.g[blockIdx.z];
    __shared__ unsigned As[2][16][136];
    __shared__ unsigned Ws[2][16][136];
    int tid = threadIdx.x;
    int w = tid >> 5, lane = tid & 31;
    int g = lane >> 2, tg = lane & 3;
    int bx = blockIdx.x, by = blockIdx.y;
    int rwarp = (w >> 1) * 32;
    int cwarp = (w & 1) * 64;

    float acc[2][8][4];
#pragma unroll
    for (int m = 0; m < 2; m++)
#pragma unroll
        for (int nt = 0; nt < 8; nt++)
#pragma unroll
            for (int e = 0; e < 4; e++) acc[m][nt][e] = 0.f;

    int arow = tid >> 2, ajj = tid & 3;     // A f4: rows 0..63 (+64 second)
    int wkr = tid >> 5, wnn = tid & 31;     // W f4: k-rows 0..7 (+8 second)
    int wpr0 = (wkr & 3) * 4 + (wkr >> 2);          // pi(wkr)
    int wpr1 = ((wkr + 8) & 3) * 4 + ((wkr + 8) >> 2);

    const float* Ab = gd.A + (size_t)(by * 128) * 512;
    const float* Wb = gd.W + bx * 128;

    float4 a0v, a1v, w0v, w1v;
    a0v = *(const float4*)(Ab + (size_t)arow * 512 + ajj * 4);
    a1v = *(const float4*)(Ab + (size_t)(arow + 64) * 512 + ajj * 4);
    w0v = *(const float4*)(Wb + (size_t)wkr * 512 + wnn * 4);
    w1v = *(const float4*)(Wb + (size_t)(wkr + 8) * 512 + wnn * 4);
    {
        // A element logical k = ajj*4+c stored at physical row c*4+ajj
        As[0][0 * 4 + ajj][arow] = cvt_tf32(a0v.x);
        As[0][1 * 4 + ajj][arow] = cvt_tf32(a0v.y);
        As[0][2 * 4 + ajj][arow] = cvt_tf32(a0v.z);
        As[0][3 * 4 + ajj][arow] = cvt_tf32(a0v.w);
        As[0][0 * 4 + ajj][arow + 64] = cvt_tf32(a1v.x);
        As[0][1 * 4 + ajj][arow + 64] = cvt_tf32(a1v.y);
        As[0][2 * 4 + ajj][arow + 64] = cvt_tf32(a1v.z);
        As[0][3 * 4 + ajj][arow + 64] = cvt_tf32(a1v.w);
        *(uint4*)&Ws[0][wpr0][wnn * 4] = make_uint4(
            cvt_tf32(w0v.x), cvt_tf32(w0v.y), cvt_tf32(w0v.z), cvt_tf32(w0v.w));
        *(uint4*)&Ws[0][wpr1][wnn * 4] = make_uint4(
            cvt_tf32(w1v.x), cvt_tf32(w1v.y), cvt_tf32(w1v.z), cvt_tf32(w1v.w));
    }
    __syncthreads();

#pragma unroll 1
    for (int kk = 0; kk < 32; kk++) {
        int buf = kk & 1;
        if (kk < 31) {
            int kb16 = (kk + 1) * 16;
            a0v = *(const float4*)(Ab + (size_t)arow * 512 + kb16 + ajj * 4);
            a1v = *(const float4*)(Ab + (size_t)(arow + 64) * 512 + kb16 + ajj * 4);
            w0v = *(const float4*)(Wb + (size_t)(kb16 + wkr) * 512 + wnn * 4);
            w1v = *(const float4*)(Wb + (size_t)(kb16 + wkr + 8) * 512 + wnn * 4);
        }
#pragma unroll
        for (int ks = 0; ks < 16; ks += 8) {
            unsigned a[2][4];
#pragma unroll
            for (int m = 0; m < 2; m++) {
                int rb = rwarp + m * 16;
                a[m][0] = As[buf][ks + tg][rb + g];
                a[m][1] = As[buf][ks + tg][rb + g + 8];
                a[m][2] = As[buf][ks + tg + 4][rb + g];
                a[m][3] = As[buf][ks + tg + 4][rb + g + 8];
            }
#pragma unroll
            for (int nt = 0; nt < 8; nt++) {
                unsigned b0 = Ws[buf][ks + tg][cwarp + nt * 8 + g];
                unsigned b1 = Ws[buf][ks + tg + 4][cwarp + nt * 8 + g];
                mma_tf32(acc[0][nt][0], acc[0][nt][1], acc[0][nt][2], acc[0][nt][3],
                         a[0][0], a[0][1], a[0][2], a[0][3], b0, b1);
                mma_tf32(acc[1][nt][0], acc[1][nt][1], acc[1][nt][2], acc[1][nt][3],
                         a[1][0], a[1][1], a[1][2], a[1][3], b0, b1);
            }
        }
        if (kk < 31) {
            int nb = buf ^ 1;
            As[nb][0 * 4 + ajj][arow] = cvt_tf32(a0v.x);
            As[nb][1 * 4 + ajj][arow] = cvt_tf32(a0v.y);
            As[nb][2 * 4 + ajj][arow] = cvt_tf32(a0v.z);
            As[nb][3 * 4 + ajj][arow] = cvt_tf32(a0v.w);
            As[nb][0 * 4 + ajj][arow + 64] = cvt_tf32(a1v.x);
            As[nb][1 * 4 + ajj][arow + 64] = cvt_tf32(a1v.y);
            As[nb][2 * 4 + ajj][arow + 64] = cvt_tf32(a1v.z);
            As[nb][3 * 4 + ajj][arow + 64] = cvt_tf32(a1v.w);
            *(uint4*)&Ws[nb][wpr0][wnn * 4] = make_uint4(
                cvt_tf32(w0v.x), cvt_tf32(w0v.y), cvt_tf32(w0v.z), cvt_tf32(w0v.w));
            *(uint4*)&Ws[nb][wpr1][wnn * 4] = make_uint4(
                cvt_tf32(w1v.x), cvt_tf32(w1v.y), cvt_tf32(w1v.z), cvt_tf32(w1v.w));
            __syncthreads();
        }
    }

    int mode = (int)gd.mode;
#pragma unroll
    for (int m = 0; m < 2; m++) {
        int r0 = by * 128 + rwarp + m * 16 + g;
#pragma unroll
        for (int nt = 0; nt < 8; nt++) {
            int c0 = bx * 128 + cwarp + nt * 8 + 2 * tg;
#pragma unroll
            for (int e = 0; e < 4; e++) {
                int gr = r0 + (e >> 1) * 8;
                int gc = c0 + (e & 1);
                float v = acc[m][nt][e] + (gd.bias ? gd.bias[gc] : 0.f);
                if (mode == 0) {
                    gd.d0[(size_t)gr * 512 + gc] = v;
                } else {
                    int h = gc >> 6, d = gc & 63;
                    int bI = gr >> 10, sI = gr & 1023;
                    size_t off = (((size_t)(bI * Hh + h) * Ss + sI) * DHd + d);
                    if (mode == 1) {
                        gd.d0[off] = v;
                    } else {
                        gd.d0[off] = v + gd.e0[gc];
                        gd.d1[off] = v + gd.e1[gc];
                    }
                }
            }
        }
    }
}

// ---------------------------------------------------------------------------
// Fused attention kernel (unchanged — validated at 1219us/3.05e-4 in R15)
// ---------------------------------------------------------------------------
__global__ __launch_bounds__(512, 2)
void attn_kernel(float* __restrict__ scratch,
                 const unsigned char* __restrict__ maskg,
                 float* __restrict__ out)
{
    extern __shared__ float sm[];
    float* qu   = sm;                 // [16][68] tf32-bit u32 (as float storage)
    float* qv   = sm + 1088;          // [17][68] tf32-bit u32
    float* kb   = sm + 2244;          // [128][68] = 8704 (tile / reduce buffer)
    float* sbuf = sm + 10948;         // [16][SST] = 16544 (scores -> prob bits)
    unsigned char* msk = (unsigned char*)(sm + 27492); // 1024 B

    int tid = threadIdx.x;
    int lane = tid & 31, w = tid >> 5;   // w 0..15
    int tile = blockIdx.x;   // 0..63
    int h = blockIdx.y;      // 0..7
    int bz = blockIdx.z;     // 0..7
    int bI = bz >> 1, st = bz & 1;

    const float* QUg = scratch + (st ? OFF_QU2 : OFF_QU1);
    const float* QVg = scratch + (st ? OFF_QV2 : OFF_QV1);
    const float* Kg  = scratch + (st ? OFF_K2  : OFF_K1);
    const float* Vg  = scratch + (st ? OFF_V2  : OFF_V1);
    const float* Pg  = scratch + OFF_POS;
    float* CTXg = scratch + (st ? OFF_CTX2 : OFF_CTX1);

    size_t bh = (size_t)(bI * Hh + h) * Ss * DHd;

    unsigned* quw = (unsigned*)qu;
    unsigned* qvw = (unsigned*)qv;

    // ---- phase 0: q loads pre-converted to tf32 bits, mask ----
#pragma unroll
    for (int it = 0; it < 2; it++) {
        int idx = it * 512 + tid;                // 0..1023
        int r = idx >> 6, d = idx & 63;
        quw[r * 68 + d] = cvt_tf32(QUg[bh + (size_t)(tile * 16 + r) * 64 + d]);
    }
#pragma unroll
    for (int it = 0; it < 3; it++) {
        int idx = it * 512 + tid;
        if (idx < 1088) {
            int r = idx >> 6, d = idx & 63;
            int gi = tile * 16 + r;
            if (gi > Ss - 1) gi = Ss - 1;        // row16 of last tile: blocked below
            qvw[r * 68 + d] = cvt_tf32(QVg[bh + (size_t)gi * 64 + d]);
        }
    }
    {
        const unsigned char* mrow = maskg + (size_t)bI * Ss;
#pragma unroll
        for (int it = 0; it < 2; it++) {
            int idx = it * 512 + tid;
            msk[idx] = mrow[idx];
        }
    }
    __syncthreads();

    unsigned qv_u = smem_u32(qv);
    unsigned kb_u = smem_u32(kb);

    int g  = lane >> 2;   // mma group 0..7
    int tg = lane & 3;    // thread-in-group 0..3

    // ================= pass 1: content -> sbuf (tf32 mma) =================
    {
        float4 fl[4];
#pragma unroll
        for (int it = 0; it < 4; it++) {
            int idx = it * 512 + tid; int s_ = idx >> 4, ds = idx & 15;
            fl[it] = *(const float4*)(Kg + bh + (size_t)s_ * 64 + ds * 4);
        }
#pragma unroll 1
        for (int c = 0; c < 8; c++) {
#pragma unroll
            for (int it = 0; it < 4; it++) {
                int idx = it * 512 + tid; int s_ = idx >> 4, ds = idx & 15;
                *(float4*)(kb + s_ * 68 + ds * 4) = fl[it];
            }
            __syncthreads();
            if (c < 7) {
#pragma unroll
                for (int it = 0; it < 4; it++) {
                    int idx = it * 512 + tid; int s_ = idx >> 4, ds = idx & 15;
                    fl[it] = *(const float4*)(Kg + bh
                                  + (size_t)((c + 1) * 128 + s_) * 64 + ds * 4);
                }
            }
            float d0 = 0.f, d1 = 0.f, d2 = 0.f, d3 = 0.f;
            const float* kcol = kb + (w * 8 + g) * 68;
#pragma unroll
            for (int ks = 0; ks < 8; ks++) {
                unsigned a0 = quw[g * 68 + ks * 8 + tg];
                unsigned a1 = quw[(g + 8) * 68 + ks * 8 + tg];
                unsigned a2 = quw[g * 68 + ks * 8 + tg + 4];
                unsigned a3 = quw[(g + 8) * 68 + ks * 8 + tg + 4];
                unsigned b0 = cvt_tf32(kcol[ks * 8 + tg]);
                unsigned b1 = cvt_tf32(kcol[ks * 8 + tg + 4]);
                mma_tf32(d0, d1, d2, d3, a0, a1, a2, a3, b0, b1);
            }
            int col = c * 128 + w * 8 + 2 * tg;
            *(float2*)&sbuf[g * SST + col] = make_float2(d0, d1);
            *(float2*)&sbuf[(g + 8) * SST + col] = make_float2(d2, d3);
            __syncthreads();
        }
    }

    // ================= pass 2: pos scatter-add into sbuf (tf32 mma) ========
    {
        float4 fl[4];
#pragma unroll
        for (int it = 0; it < 4; it++) {
            int idx = it * 512 + tid; int s_ = idx >> 4, ds = idx & 15;
            fl[it] = *(const float4*)(Pg + bh + (size_t)s_ * 64 + ds * 4);
        }
#pragma unroll 1
        for (int c = 0; c < 8; c++) {
#pragma unroll
            for (int it = 0; it < 4; it++) {
                int idx = it * 512 + tid; int s_ = idx >> 4, ds = idx & 15;
                *(float4*)(kb + s_ * 68 + ds * 4) = fl[it];
            }
            __syncthreads();
            if (c < 7) {
#pragma unroll
                for (int it = 0; it < 4; it++) {
                    int idx = it * 512 + tid; int s_ = idx >> 4, ds = idx & 15;
                    fl[it] = *(const float4*)(Pg + bh
                                  + (size_t)((c + 1) * 128 + s_) * 64 + ds * 4);
                }
            }
            float d0 = 0.f, d1 = 0.f, d2 = 0.f, d3 = 0.f;
            const float* pcol = kb + (w * 8 + g) * 68;
#pragma unroll
            for (int ks = 0; ks < 8; ks++) {
                unsigned a0 = qvw[g * 68 + ks * 8 + tg];
                unsigned a1 = qvw[(g + 8) * 68 + ks * 8 + tg];
                unsigned a2 = qvw[g * 68 + ks * 8 + tg + 4];
                unsigned a3 = qvw[(g + 8) * 68 + ks * 8 + tg + 4];
                unsigned b0 = cvt_tf32(pcol[ks * 8 + tg]);
                unsigned b1 = cvt_tf32(pcol[ks * 8 + tg + 4]);
                mma_tf32(d0, d1, d2, d3, a0, a1, a2, a3, b0, b1);
            }
            int cg0 = c * 128 + w * 8 + 2 * tg;
            float vv[4] = { d0, d1, d2, d3 };
            int rr[4]   = { g, g, g + 8, g + 8 };
            int cc[4]   = { cg0, cg0 + 1, cg0, cg0 + 1 };
#pragma unroll
            for (int j = 0; j < 4; j++) {
                int row = rr[j], cg = cc[j];
                int gg = tile * 16 + row;
                bool condA = (cg >= Ss - 1 - gg);
                int addr = condA ? (row * SST + (cg + gg + 1 - Ss))
                                 : ((row - 1) * SST + (cg + gg + 1));
                if (condA || row > 0) sbuf[addr] += vv[j];
            }
            if (w < 4) {   // extra pos row 16 -> contributes only to row 15 (fp32)
                int col16 = w * 32 + lane;
                unsigned q16_u = qv_u + 16u * 272;
                unsigned pc_u = kb_u + (unsigned)col16 * 272;
                ull a = 0;
#pragma unroll
                for (int dq = 0; dq < 16; dq++) {
                    ull q01, q23; lds2x64(q01, q23, q16_u + dq * 16);
                    ull p01, p23; lds2x64(p01, p23, pc_u + dq * 16);
                    fma2(a, q01, p01); fma2(a, q23, p23);
                }
                int g16 = tile * 16 + 16;
                int cg16 = c * 128 + col16;
                if (g16 <= Ss - 1 && cg16 <= Ss - 2 - g16)
                    sbuf[15 * SST + (cg16 + g16 + 1)] += red2(a);
            }
            __syncthreads();
        }
    }

    // ---- softmax (warp = 1 row), register array ----
    int r = w;
    int ig = tile * 16 + r;
    float s[32];

    float mx = -1e30f;
#pragma unroll
    for (int jp = 0; jp < 32; jp++) {
        int t = jp * 32 + lane;
        float sc = sbuf[r * SST + t] * kScale;
        if (msk[t]) sc = -1e9f;
        s[jp] = sc;
        mx = fmaxf(mx, sc);
    }
#pragma unroll
    for (int o = 16; o > 0; o >>= 1)
        mx = fmaxf(mx, __shfl_xor_sync(0xffffffffu, mx, o));
    float sum = 0.f;
#pragma unroll
    for (int jp = 0; jp < 32; jp++) {
        float e = __expf(s[jp] - mx); s[jp] = e; sum += e;
    }
#pragma unroll
    for (int o = 16; o > 0; o >>= 1)
        sum += __shfl_xor_sync(0xffffffffu, sum, o);
    float inv = 1.f / sum;

    __syncthreads();

    // ---- phase D: fp32 probs to gmem; tf32-bit probs into sbuf ----
    size_t aout = (st ? OFF_ATTN2 : OFF_ATTN1) + ((size_t)(bI * Hh + h) * Ss) * Ss;
    unsigned* sbw = (unsigned*)sbuf;
#pragma unroll
    for (int jp = 0; jp < 32; jp++) {
        int t = jp * 32 + lane;
        float p = s[jp] * inv;
        out[aout + (size_t)ig * Ss + t] = p;
        sbw[r * SST + t] = cvt_tf32(p);
    }
    __syncthreads();

    // ---- phase E: ctx = probs @ V via tf32 mma ----
    {
        int nbase = (w & 7) * 8;
        int kh = w >> 3;

        float d0 = 0.f, d1 = 0.f, d2 = 0.f, d3 = 0.f;

        float4 fl[4];
#pragma unroll
        for (int it = 0; it < 4; it++) {
            int idx = it * 512 + tid; int s_ = idx >> 4, ds = idx & 15;
            fl[it] = *(const float4*)(Vg + bh + (size_t)s_ * 64 + ds * 4);
        }
#pragma unroll 1
        for (int c = 0; c < 8; c++) {
#pragma unroll
            for (int it = 0; it < 4; it++) {
                int idx = it * 512 + tid; int s_ = idx >> 4, ds = idx & 15;
                *(float4*)(kb + s_ * 68 + ds * 4) = fl[it];
            }
            __syncthreads();
            if (c < 7) {
#pragma unroll
                for (int it = 0; it < 4; it++) {
                    int idx = it * 512 + tid; int s_ = idx >> 4, ds = idx & 15;
                    fl[it] = *(const float4*)(Vg + bh
                                  + (size_t)((c + 1) * 128 + s_) * 64 + ds * 4);
                }
            }
            int cbase = c * 128 + kh * 64;
            const float* vb2 = kb + (kh * 64) * 68 + nbase + g;
#pragma unroll
            for (int ks = 0; ks < 8; ks++) {
                int t0 = ks * 8;
                unsigned a0 = sbw[g * SST + cbase + t0 + tg];
                unsigned a1 = sbw[(g + 8) * SST + cbase + t0 + tg];
                unsigned a2 = sbw[g * SST + cbase + t0 + tg + 4];
                unsigned a3 = sbw[(g + 8) * SST + cbase + t0 + tg + 4];
                unsigned b0 = cvt_tf32(vb2[(t0 + tg) * 68]);
                unsigned b1 = cvt_tf32(vb2[(t0 + tg + 4) * 68]);
                mma_tf32(d0, d1, d2, d3, a0, a1, a2, a3, b0, b1);
            }
            __syncthreads();
        }

        // partials -> kb[kh][row][col] (stride 68), then 2-way reduce
        {
            float* red = kb + kh * 1100;
            *(float2*)&red[g * 68 + nbase + 2 * tg] = make_float2(d0, d1);
            *(float2*)&red[(g + 8) * 68 + nbase + 2 * tg] = make_float2(d2, d3);
        }
        __syncthreads();
        {
            int o = tid * 2;                  // 0..1022, 2 outputs per thread
            int row = o >> 6, dd = o & 63;
            float2 p0 = *(const float2*)&kb[row * 68 + dd];
            float2 p1 = *(const float2*)&kb[1100 + row * 68 + dd];
            float2 rr2 = make_float2(p0.x + p1.x, p0.y + p1.y);
            int gi = tile * 16 + row;
            *(float2*)(CTXg + ((size_t)(bI * Ss + gi)) * Dd + h * DHd + dd) = rr2;
        }
    }
}

// ---------------------------------------------------------------------------
extern "C" void kernel_launch(void* const* d_in, const int* in_sizes, int n_in,
                              void* d_out, int out_size)
{
    const float* x1  = (const float*)d_in[0];
    const float* x2  = (const float*)d_in[1];
    const float* pe  = (const float*)d_in[2];
    const unsigned char* mask = (const unsigned char*)d_in[3];
    const float* Wq  = (const float*)d_in[4];
    const float* bq  = (const float*)d_in[5];
    const float* Wk  = (const float*)d_in[6];
    const float* bk  = (const float*)d_in[7];
    const float* Wv  = (const float*)d_in[8];
    const float* bv  = (const float*)d_in[9];
    const float* Wp  = (const float*)d_in[10];
    const float* ub  = (const float*)d_in[11];
    const float* vb  = (const float*)d_in[12];
    const float* Wo1 = (const float*)d_in[13];
    const float* bo1 = (const float*)d_in[14];
    const float* Wo2 = (const float*)d_in[15];
    const float* bo2 = (const float*)d_in[16];
    float* out = (float*)d_out;

    float* scratch = nullptr;
    cudaGetSymbolAddress((void**)&scratch, g_scratch);

    const int attn_smem = 27492 * 4 + 1024;  // 110,992 B -> 2 blocks/SM
    cudaFuncSetAttribute(attn_kernel, cudaFuncAttributeMaxDynamicSharedMemorySize,
                         attn_smem);

    // batched projections (7 GEMMs in one launch, tf32)
    GDescArr pj{};
    pj.g[0] = { x1, Wq, bq, scratch + OFF_QU1, scratch + OFF_QV1, ub, vb, 2 };
    pj.g[1] = { x1, Wk, bk, scratch + OFF_K1,  nullptr, nullptr, nullptr, 1 };
    pj.g[2] = { x1, Wv, bv, scratch + OFF_V1,  nullptr, nullptr, nullptr, 1 };
    pj.g[3] = { x2, Wq, bq, scratch + OFF_QU2, scratch + OFF_QV2, ub, vb, 2 };
    pj.g[4] = { x2, Wk, bk, scratch + OFF_K2,  nullptr, nullptr, nullptr, 1 };
    pj.g[5] = { x2, Wv, bv, scratch + OFF_V2,  nullptr, nullptr, nullptr, 1 };
    pj.g[6] = { pe, Wp, nullptr, scratch + OFF_POS, nullptr, nullptr, nullptr, 1 };
    sgemm_tf32<<<dim3(4, 32, 7), 256>>>(pj);

    // fused attention: tf32 scores + rel-shift(scatter) + softmax + tf32 ctx
    attn_kernel<<<dim3(64, 8, 8), 512, attn_smem>>>(scratch, mask, out);

    // batched output projections (2 GEMMs in one launch, tf32)
    GDescArr po{};
    po.g[0] = { scratch + OFF_CTX1, Wo1, bo1, out + OFF_CTX1OUT, nullptr, nullptr, nullptr, 0 };
    po.g[1] = { scratch + OFF_CTX2, Wo2, bo2, out + OFF_CTX2OUT, nullptr, nullptr, nullptr, 0 };
    sgemm_tf32<<<dim3(4, 32, 2), 256>>>(po);
}